// round 11
// baseline (speedup 1.0000x reference)
#include <cuda_runtime.h>
#include <cuda_bf16.h>

// Thread-per-row hierarchical softmax. Round-4 phase chain (node row written
// from live registers, no recover pass) at 5 blocks/SM: streaming loops are
// unroll-4 to keep regs <= 102 alongside live v[65].
// Fused output layout (flat): [ leaf_path_probs (N*65) | node_probs (N*76) ]

#define NT   128
#define ROWS 128

__global__ __launch_bounds__(NT, 5)
void molemap_kernel(const float* __restrict__ x,
                    float* __restrict__ out_path,
                    float* __restrict__ out_node)
{
    // ONLY smem: one reused buffer. input rows -> path probs (stride 65) -> node rows (stride 76)
    __shared__ __align__(16) float buf[ROWS * 76];   // 38912 B

    const int tid = threadIdx.x;
    const long long row0 = (long long)blockIdx.x * ROWS;

    // ---- Phase A: coalesced vectorized load, 128*65 = 2080 float4 ----
    {
        const float4* in4 = reinterpret_cast<const float4*>(x + row0 * 65);
        float4* b4 = reinterpret_cast<float4*>(buf);
        #pragma unroll 4
        for (int k = 0; k < 17; ++k) {
            int idx = tid + k * NT;
            if (idx < 2080) b4[idx] = in4[idx];
        }
    }
    __syncthreads();

    // ---- Phase B: thread-per-row compute; path probs written in place ----
    float v[65];          // leaf exps -> leaf probs; stays live through phase D
    float pl2[8], pt0, pt1;
    {
        float* rx = buf + tid * 65;   // stride 65 ≡ 1 (mod 32): conflict-free
        #pragma unroll
        for (int i = 0; i < 65; ++i) v[i] = rx[i];

        float grcp[8], mean[8];
#define GROUP_STATS(G, A, B, RSZ)                                       \
        {                                                               \
            float mm = v[A], s = 0.f;                                   \
            _Pragma("unroll")                                           \
            for (int i = A; i < B; ++i) { s += v[i]; mm = fmaxf(mm, v[i]); } \
            float e = 0.f;                                              \
            _Pragma("unroll")                                           \
            for (int i = A; i < B; ++i) { v[i] = __expf(v[i] - mm); e += v[i]; } \
            grcp[G] = 1.0f / e; mean[G] = s * (RSZ);                    \
        }
        GROUP_STATS(0,  0,  7, 1.0f/7.0f)
        GROUP_STATS(1,  7, 30, 1.0f/23.0f)
        GROUP_STATS(2, 30, 48, 1.0f/18.0f)
        GROUP_STATS(3, 48, 53, 1.0f/5.0f)
        GROUP_STATS(4, 53, 58, 1.0f/5.0f)
        GROUP_STATS(5, 58, 59, 1.0f)
        GROUP_STATS(6, 59, 62, 1.0f/3.0f)
        GROUP_STATS(7, 62, 65, 1.0f/3.0f)
#undef GROUP_STATS

        // level-2 softmaxes + top softmax
        {
            float mx0 = fmaxf(fmaxf(mean[0], mean[1]), fmaxf(mean[2], mean[3]));
            float e0 = __expf(mean[0]-mx0), e1 = __expf(mean[1]-mx0);
            float e2 = __expf(mean[2]-mx0), e3 = __expf(mean[3]-mx0);
            float r0 = 1.0f / (e0 + e1 + e2 + e3);
            pl2[0] = e0*r0; pl2[1] = e1*r0; pl2[2] = e2*r0; pl2[3] = e3*r0;

            float mx1 = fmaxf(fmaxf(mean[4], mean[5]), fmaxf(mean[6], mean[7]));
            float f0 = __expf(mean[4]-mx1), f1 = __expf(mean[5]-mx1);
            float f2 = __expf(mean[6]-mx1), f3 = __expf(mean[7]-mx1);
            float r1 = 1.0f / (f0 + f1 + f2 + f3);
            pl2[4] = f0*r1; pl2[5] = f1*r1; pl2[6] = f2*r1; pl2[7] = f3*r1;

            float m0 = (mean[0]*7.f + mean[1]*23.f + mean[2]*18.f + mean[3]*5.f) * (1.0f/53.0f);
            float m1 = (mean[4]*5.f + mean[5]*1.f + mean[6]*3.f + mean[7]*3.f) * (1.0f/12.0f);
            float mxt = fmaxf(m0, m1);
            float t0 = __expf(m0 - mxt), t1 = __expf(m1 - mxt);
            float rt = 1.0f / (t0 + t1);
            pt0 = t0 * rt; pt1 = t1 * rt;
        }

        // v -> leaf probs; path = leaf * pl2 * pt written to smem
        float ks[8];
        #pragma unroll
        for (int g = 0; g < 8; ++g) ks[g] = pl2[g] * (g < 4 ? pt0 : pt1);

#define FINALIZE(G, A, B)                                       \
        {                                                       \
            float rc = grcp[G], kk = ks[G];                     \
            _Pragma("unroll")                                   \
            for (int i = A; i < B; ++i) {                       \
                v[i] *= rc;            /* leaf prob */          \
                rx[i] = v[i] * kk;     /* path prob */          \
            }                                                   \
        }
        FINALIZE(0,  0,  7)  FINALIZE(1,  7, 30)
        FINALIZE(2, 30, 48)  FINALIZE(3, 48, 53)
        FINALIZE(4, 53, 58)  FINALIZE(5, 58, 59)
        FINALIZE(6, 59, 62)  FINALIZE(7, 62, 65)
#undef FINALIZE
    }
    __syncthreads();

    // ---- Phase C: stream path probs out, 2080 float4 (read-only on buf) ----
    {
        float4* op4 = reinterpret_cast<float4*>(out_path + row0 * 65);
        const float4* b4 = reinterpret_cast<const float4*>(buf);
        #pragma unroll 4
        for (int k = 0; k < 17; ++k) {
            int idx = tid + k * NT;
            if (idx < 2080) op4[idx] = b4[idx];
        }
    }
    __syncthreads();   // path reads done before node-layout overwrite

    // ---- Phase D: write node rows [128][76] from live registers ----
    {
        float* rn = buf + tid * 76;
        #pragma unroll
        for (int i = 0; i < 65; ++i) rn[i] = v[i];
        #pragma unroll
        for (int g = 0; g < 8; ++g) rn[65 + g] = pl2[g];
        rn[73] = pt0;
        rn[74] = pt1;
        rn[75] = 1.0f;
    }
    __syncthreads();

    // ---- Phase E: stream node_probs out, 128*76 = 2432 float4 exact ----
    {
        float4* on4 = reinterpret_cast<float4*>(out_node + row0 * 76);
        const float4* b4 = reinterpret_cast<const float4*>(buf);
        #pragma unroll 4
        for (int k = 0; k < 19; ++k) {
            int idx = tid + k * NT;
            on4[idx] = b4[idx];
        }
    }
}

extern "C" void kernel_launch(void* const* d_in, const int* in_sizes, int n_in,
                              void* d_out, int out_size)
{
    const float* x = (const float*)d_in[0];
    const long long N = (long long)in_sizes[0] / 65;   // 524288
    float* out_path = (float*)d_out;
    float* out_node = out_path + N * 65;

    const int blocks = (int)(N / ROWS);                // 4096
    molemap_kernel<<<blocks, NT>>>(x, out_path, out_node);
}

// round 12
// speedup vs baseline: 1.1287x; 1.1287x over previous
#include <cuda_runtime.h>
#include <cuda_bf16.h>

// Thread-per-row hierarchical softmax. 2-sync dual-buffer design:
// load -> sync -> compute (write BOTH output layouts from registers) -> sync ->
// stream both outputs back-to-back (36 independent float4 per thread, max MLP).
// Block = 64 threads / 64 rows; 36KB smem -> 6 blocks/SM; regs unbounded (no spill).
// Fused output layout (flat): [ leaf_path_probs (N*65) | node_probs (N*76) ]

#define NT   64
#define ROWS 64

__global__ void molemap_kernel(const float* __restrict__ x,
                               float* __restrict__ out_path,
                               float* __restrict__ out_node)
{
    __shared__ __align__(16) float bufP[ROWS * 65];   // input rows -> path probs (16640 B)
    __shared__ __align__(16) float bufN[ROWS * 76];   // node rows             (19456 B)

    const int tid = threadIdx.x;
    const long long row0 = (long long)blockIdx.x * ROWS;

    // ---- Phase A: coalesced vectorized load, 64*65 = 4160 floats = 1040 float4 ----
    {
        const float4* in4 = reinterpret_cast<const float4*>(x + row0 * 65);
        float4* b4 = reinterpret_cast<float4*>(bufP);
        #pragma unroll
        for (int k = 0; k < 17; ++k) {
            int idx = tid + k * NT;
            if (idx < 1040) b4[idx] = in4[idx];
        }
    }
    __syncthreads();

    // ---- Phase B: thread-per-row compute; write path (bufP) AND node (bufN) rows ----
    {
        float* rx = bufP + tid * 65;   // stride 65 ≡ 1 (mod 32): conflict-free
        float* rn = bufN + tid * 76;
        float v[65];
        #pragma unroll
        for (int i = 0; i < 65; ++i) v[i] = rx[i];

        float grcp[8], mean[8];
#define GROUP_STATS(G, A, B, RSZ)                                       \
        {                                                               \
            float mm = v[A], s = 0.f;                                   \
            _Pragma("unroll")                                           \
            for (int i = A; i < B; ++i) { s += v[i]; mm = fmaxf(mm, v[i]); } \
            float e = 0.f;                                              \
            _Pragma("unroll")                                           \
            for (int i = A; i < B; ++i) { v[i] = __expf(v[i] - mm); e += v[i]; } \
            grcp[G] = 1.0f / e; mean[G] = s * (RSZ);                    \
        }
        GROUP_STATS(0,  0,  7, 1.0f/7.0f)
        GROUP_STATS(1,  7, 30, 1.0f/23.0f)
        GROUP_STATS(2, 30, 48, 1.0f/18.0f)
        GROUP_STATS(3, 48, 53, 1.0f/5.0f)
        GROUP_STATS(4, 53, 58, 1.0f/5.0f)
        GROUP_STATS(5, 58, 59, 1.0f)
        GROUP_STATS(6, 59, 62, 1.0f/3.0f)
        GROUP_STATS(7, 62, 65, 1.0f/3.0f)
#undef GROUP_STATS

        // level-2 softmaxes + top softmax
        float pl2[8], pt0, pt1;
        {
            float mx0 = fmaxf(fmaxf(mean[0], mean[1]), fmaxf(mean[2], mean[3]));
            float e0 = __expf(mean[0]-mx0), e1 = __expf(mean[1]-mx0);
            float e2 = __expf(mean[2]-mx0), e3 = __expf(mean[3]-mx0);
            float r0 = 1.0f / (e0 + e1 + e2 + e3);
            pl2[0] = e0*r0; pl2[1] = e1*r0; pl2[2] = e2*r0; pl2[3] = e3*r0;

            float mx1 = fmaxf(fmaxf(mean[4], mean[5]), fmaxf(mean[6], mean[7]));
            float f0 = __expf(mean[4]-mx1), f1 = __expf(mean[5]-mx1);
            float f2 = __expf(mean[6]-mx1), f3 = __expf(mean[7]-mx1);
            float r1 = 1.0f / (f0 + f1 + f2 + f3);
            pl2[4] = f0*r1; pl2[5] = f1*r1; pl2[6] = f2*r1; pl2[7] = f3*r1;

            float m0 = (mean[0]*7.f + mean[1]*23.f + mean[2]*18.f + mean[3]*5.f) * (1.0f/53.0f);
            float m1 = (mean[4]*5.f + mean[5]*1.f + mean[6]*3.f + mean[7]*3.f) * (1.0f/12.0f);
            float mxt = fmaxf(m0, m1);
            float t0 = __expf(m0 - mxt), t1 = __expf(m1 - mxt);
            float rt = 1.0f / (t0 + t1);
            pt0 = t0 * rt; pt1 = t1 * rt;
        }

        // leaf prob -> node row; path prob -> path row (both from registers)
        float ks[8];
        #pragma unroll
        for (int g = 0; g < 8; ++g) ks[g] = pl2[g] * (g < 4 ? pt0 : pt1);

#define FINALIZE(G, A, B)                                       \
        {                                                       \
            float rc = grcp[G], kk = ks[G];                     \
            _Pragma("unroll")                                   \
            for (int i = A; i < B; ++i) {                       \
                float lp = v[i] * rc;                           \
                rn[i] = lp;            /* leaf prob */          \
                rx[i] = lp * kk;       /* path prob */          \
            }                                                   \
        }
        FINALIZE(0,  0,  7)  FINALIZE(1,  7, 30)
        FINALIZE(2, 30, 48)  FINALIZE(3, 48, 53)
        FINALIZE(4, 53, 58)  FINALIZE(5, 58, 59)
        FINALIZE(6, 59, 62)  FINALIZE(7, 62, 65)
#undef FINALIZE

        #pragma unroll
        for (int g = 0; g < 8; ++g) rn[65 + g] = pl2[g];
        rn[73] = pt0;
        rn[74] = pt1;
        rn[75] = 1.0f;
    }   // everything register-dead here
    __syncthreads();

    // ---- Phase C: stream BOTH outputs back-to-back, no intervening sync ----
    {
        // path: 64*65 = 1040 float4
        float4* op4 = reinterpret_cast<float4*>(out_path + row0 * 65);
        const float4* p4 = reinterpret_cast<const float4*>(bufP);
        #pragma unroll
        for (int k = 0; k < 17; ++k) {
            int idx = tid + k * NT;
            if (idx < 1040) op4[idx] = p4[idx];
        }

        // node: 64*76 = 1216 float4 exact (19 iters * 64 threads)
        float4* on4 = reinterpret_cast<float4*>(out_node + row0 * 76);
        const float4* n4 = reinterpret_cast<const float4*>(bufN);
        #pragma unroll
        for (int k = 0; k < 19; ++k) {
            int idx = tid + k * NT;
            on4[idx] = n4[idx];
        }
    }
}

extern "C" void kernel_launch(void* const* d_in, const int* in_sizes, int n_in,
                              void* d_out, int out_size)
{
    const float* x = (const float*)d_in[0];
    const long long N = (long long)in_sizes[0] / 65;   // 524288
    float* out_path = (float*)d_out;
    float* out_node = out_path + N * 65;

    const int blocks = (int)(N / ROWS);                // 8192
    molemap_kernel<<<blocks, NT>>>(x, out_path, out_node);
}

// round 14
// speedup vs baseline: 1.2960x; 1.1482x over previous
#include <cuda_runtime.h>
#include <cuda_bf16.h>

// Warp-autonomous thread-per-row hierarchical softmax.
// Each WARP owns 32 rows end-to-end: load -> compute -> store, with only
// __syncwarp between its phases. No __syncthreads anywhere: 16 independent
// warp-pipelines per SM keep DRAM busy across phase boundaries.
// Fused output layout (flat): [ leaf_path_probs (N*65) | node_probs (N*76) ]

#define NT        128
#define WARPS     (NT / 32)
#define ROWS_W    32                 // rows per warp
#define ROWS_B    (WARPS * ROWS_W)   // 128 rows per block
#define WREG      (ROWS_W * 76)      // floats per warp smem region (2432)

__global__ __launch_bounds__(NT)
void molemap_kernel(const float* __restrict__ x,
                    float* __restrict__ out_path,
                    float* __restrict__ out_node)
{
    // per-warp private regions; reused: input rows (stride 65) -> path probs -> node rows (stride 76)
    __shared__ __align__(16) float buf[WARPS * WREG];   // 38912 B

    const int tid  = threadIdx.x;
    const int w    = tid >> 5;
    const int lane = tid & 31;
    float* wbuf = buf + w * WREG;    // warp region base (2432 floats, %32==0)

    const long long wrow0 = (long long)blockIdx.x * ROWS_B + w * ROWS_W;

    // ---- Phase A: warp-coalesced load of 32 rows: 32*65 = 2080 floats = 520 float4 ----
    {
        const float4* in4 = reinterpret_cast<const float4*>(x + wrow0 * 65);
        float4* b4 = reinterpret_cast<float4*>(wbuf);
        #pragma unroll
        for (int k = 0; k < 17; ++k) {
            int idx = lane + k * 32;
            if (idx < 520) b4[idx] = in4[idx];
        }
    }
    __syncwarp();

    // ---- Phase B: thread-per-row compute; path probs written in place ----
    float v[65];          // leaf exps -> leaf probs; live through node write
    float pl2[8], pt0, pt1;
    {
        float* rx = wbuf + lane * 65;   // stride 65 ≡ 1 (mod 32): conflict-free
        #pragma unroll
        for (int i = 0; i < 65; ++i) v[i] = rx[i];

        float grcp[8], mean[8];
#define GROUP_STATS(G, A, B, RSZ)                                       \
        {                                                               \
            float mm = v[A], s = 0.f;                                   \
            _Pragma("unroll")                                           \
            for (int i = A; i < B; ++i) { s += v[i]; mm = fmaxf(mm, v[i]); } \
            float e = 0.f;                                              \
            _Pragma("unroll")                                           \
            for (int i = A; i < B; ++i) { v[i] = __expf(v[i] - mm); e += v[i]; } \
            grcp[G] = 1.0f / e; mean[G] = s * (RSZ);                    \
        }
        GROUP_STATS(0,  0,  7, 1.0f/7.0f)
        GROUP_STATS(1,  7, 30, 1.0f/23.0f)
        GROUP_STATS(2, 30, 48, 1.0f/18.0f)
        GROUP_STATS(3, 48, 53, 1.0f/5.0f)
        GROUP_STATS(4, 53, 58, 1.0f/5.0f)
        GROUP_STATS(5, 58, 59, 1.0f)
        GROUP_STATS(6, 59, 62, 1.0f/3.0f)
        GROUP_STATS(7, 62, 65, 1.0f/3.0f)
#undef GROUP_STATS

        // level-2 softmaxes + top softmax
        {
            float mx0 = fmaxf(fmaxf(mean[0], mean[1]), fmaxf(mean[2], mean[3]));
            float e0 = __expf(mean[0]-mx0), e1 = __expf(mean[1]-mx0);
            float e2 = __expf(mean[2]-mx0), e3 = __expf(mean[3]-mx0);
            float r0 = 1.0f / (e0 + e1 + e2 + e3);
            pl2[0] = e0*r0; pl2[1] = e1*r0; pl2[2] = e2*r0; pl2[3] = e3*r0;

            float mx1 = fmaxf(fmaxf(mean[4], mean[5]), fmaxf(mean[6], mean[7]));
            float f0 = __expf(mean[4]-mx1), f1 = __expf(mean[5]-mx1);
            float f2 = __expf(mean[6]-mx1), f3 = __expf(mean[7]-mx1);
            float r1 = 1.0f / (f0 + f1 + f2 + f3);
            pl2[4] = f0*r1; pl2[5] = f1*r1; pl2[6] = f2*r1; pl2[7] = f3*r1;

            float m0 = (mean[0]*7.f + mean[1]*23.f + mean[2]*18.f + mean[3]*5.f) * (1.0f/53.0f);
            float m1 = (mean[4]*5.f + mean[5]*1.f + mean[6]*3.f + mean[7]*3.f) * (1.0f/12.0f);
            float mxt = fmaxf(m0, m1);
            float t0 = __expf(m0 - mxt), t1 = __expf(m1 - mxt);
            float rt = 1.0f / (t0 + t1);
            pt0 = t0 * rt; pt1 = t1 * rt;
        }

        // v -> leaf probs; path = leaf * pl2 * pt written to smem
        float ks[8];
        #pragma unroll
        for (int g = 0; g < 8; ++g) ks[g] = pl2[g] * (g < 4 ? pt0 : pt1);

#define FINALIZE(G, A, B)                                       \
        {                                                       \
            float rc = grcp[G], kk = ks[G];                     \
            _Pragma("unroll")                                   \
            for (int i = A; i < B; ++i) {                       \
                v[i] *= rc;            /* leaf prob */          \
                rx[i] = v[i] * kk;     /* path prob */          \
            }                                                   \
        }
        FINALIZE(0,  0,  7)  FINALIZE(1,  7, 30)
        FINALIZE(2, 30, 48)  FINALIZE(3, 48, 53)
        FINALIZE(4, 53, 58)  FINALIZE(5, 58, 59)
        FINALIZE(6, 59, 62)  FINALIZE(7, 62, 65)
#undef FINALIZE
    }
    __syncwarp();

    // ---- Phase C: warp-coalesced stream of path probs: 520 float4 ----
    {
        float4* op4 = reinterpret_cast<float4*>(out_path + wrow0 * 65);
        const float4* b4 = reinterpret_cast<const float4*>(wbuf);
        #pragma unroll
        for (int k = 0; k < 17; ++k) {
            int idx = lane + k * 32;
            if (idx < 520) op4[idx] = b4[idx];
        }
    }
    __syncwarp();   // warp's path reads done before node overwrite

    // ---- Phase D: write node rows [32][76] from live registers ----
    {
        float* rn = wbuf + lane * 76;
        #pragma unroll
        for (int i = 0; i < 65; ++i) rn[i] = v[i];
        #pragma unroll
        for (int g = 0; g < 8; ++g) rn[65 + g] = pl2[g];
        rn[73] = pt0;
        rn[74] = pt1;
        rn[75] = 1.0f;
    }
    __syncwarp();

    // ---- Phase E: warp-coalesced stream of node rows: 32*76 = 608 float4 exact ----
    {
        float4* on4 = reinterpret_cast<float4*>(out_node + wrow0 * 76);
        const float4* b4 = reinterpret_cast<const float4*>(wbuf);
        #pragma unroll
        for (int k = 0; k < 19; ++k) {
            int idx = lane + k * 32;
            on4[idx] = b4[idx];
        }
    }
}

extern "C" void kernel_launch(void* const* d_in, const int* in_sizes, int n_in,
                              void* d_out, int out_size)
{
    const float* x = (const float*)d_in[0];
    const long long N = (long long)in_sizes[0] / 65;   // 524288
    float* out_path = (float*)d_out;
    float* out_node = out_path + N * 65;

    const int blocks = (int)(N / ROWS_B);              // 4096
    molemap_kernel<<<blocks, NT>>>(x, out_path, out_node);
}

// round 15
// speedup vs baseline: 1.3221x; 1.0201x over previous
#include <cuda_runtime.h>
#include <cuda_bf16.h>

// Warp-autonomous thread-per-row hierarchical softmax.
// Each WARP owns 32 rows end-to-end (load -> compute -> store, __syncwarp only).
// NT=64: two autonomous warps per block -> 8 blocks/SM (regs 8*64*122 <= 64K,
// smem 8*19456B <= 228KB), halving wave-quantization tail vs NT=128.
// Fused output layout (flat): [ leaf_path_probs (N*65) | node_probs (N*76) ]

#define NT        64
#define WARPS     (NT / 32)
#define ROWS_W    32                 // rows per warp
#define ROWS_B    (WARPS * ROWS_W)   // 64 rows per block
#define WREG      (ROWS_W * 76)      // floats per warp smem region (2432)

__global__ __launch_bounds__(NT)
void molemap_kernel(const float* __restrict__ x,
                    float* __restrict__ out_path,
                    float* __restrict__ out_node)
{
    // per-warp private regions; reused: input rows (stride 65) -> path probs -> node rows (stride 76)
    __shared__ __align__(16) float buf[WARPS * WREG];   // 19456 B

    const int tid  = threadIdx.x;
    const int w    = tid >> 5;
    const int lane = tid & 31;
    float* wbuf = buf + w * WREG;    // warp region base (2432 floats, %32==0)

    const long long wrow0 = (long long)blockIdx.x * ROWS_B + w * ROWS_W;

    // ---- Phase A: warp-coalesced load of 32 rows: 32*65 = 2080 floats = 520 float4 ----
    {
        const float4* in4 = reinterpret_cast<const float4*>(x + wrow0 * 65);
        float4* b4 = reinterpret_cast<float4*>(wbuf);
        #pragma unroll
        for (int k = 0; k < 17; ++k) {
            int idx = lane + k * 32;
            if (idx < 520) b4[idx] = in4[idx];
        }
    }
    __syncwarp();

    // ---- Phase B: thread-per-row compute; path probs written in place ----
    float v[65];          // leaf exps -> leaf probs; live through node write
    float pl2[8], pt0, pt1;
    {
        float* rx = wbuf + lane * 65;   // stride 65 ≡ 1 (mod 32): conflict-free
        #pragma unroll
        for (int i = 0; i < 65; ++i) v[i] = rx[i];

        float grcp[8], mean[8];
#define GROUP_STATS(G, A, B, RSZ)                                       \
        {                                                               \
            float mm = v[A], s = 0.f;                                   \
            _Pragma("unroll")                                           \
            for (int i = A; i < B; ++i) { s += v[i]; mm = fmaxf(mm, v[i]); } \
            float e = 0.f;                                              \
            _Pragma("unroll")                                           \
            for (int i = A; i < B; ++i) { v[i] = __expf(v[i] - mm); e += v[i]; } \
            grcp[G] = 1.0f / e; mean[G] = s * (RSZ);                    \
        }
        GROUP_STATS(0,  0,  7, 1.0f/7.0f)
        GROUP_STATS(1,  7, 30, 1.0f/23.0f)
        GROUP_STATS(2, 30, 48, 1.0f/18.0f)
        GROUP_STATS(3, 48, 53, 1.0f/5.0f)
        GROUP_STATS(4, 53, 58, 1.0f/5.0f)
        GROUP_STATS(5, 58, 59, 1.0f)
        GROUP_STATS(6, 59, 62, 1.0f/3.0f)
        GROUP_STATS(7, 62, 65, 1.0f/3.0f)
#undef GROUP_STATS

        // level-2 softmaxes + top softmax
        {
            float mx0 = fmaxf(fmaxf(mean[0], mean[1]), fmaxf(mean[2], mean[3]));
            float e0 = __expf(mean[0]-mx0), e1 = __expf(mean[1]-mx0);
            float e2 = __expf(mean[2]-mx0), e3 = __expf(mean[3]-mx0);
            float r0 = 1.0f / (e0 + e1 + e2 + e3);
            pl2[0] = e0*r0; pl2[1] = e1*r0; pl2[2] = e2*r0; pl2[3] = e3*r0;

            float mx1 = fmaxf(fmaxf(mean[4], mean[5]), fmaxf(mean[6], mean[7]));
            float f0 = __expf(mean[4]-mx1), f1 = __expf(mean[5]-mx1);
            float f2 = __expf(mean[6]-mx1), f3 = __expf(mean[7]-mx1);
            float r1 = 1.0f / (f0 + f1 + f2 + f3);
            pl2[4] = f0*r1; pl2[5] = f1*r1; pl2[6] = f2*r1; pl2[7] = f3*r1;

            float m0 = (mean[0]*7.f + mean[1]*23.f + mean[2]*18.f + mean[3]*5.f) * (1.0f/53.0f);
            float m1 = (mean[4]*5.f + mean[5]*1.f + mean[6]*3.f + mean[7]*3.f) * (1.0f/12.0f);
            float mxt = fmaxf(m0, m1);
            float t0 = __expf(m0 - mxt), t1 = __expf(m1 - mxt);
            float rt = 1.0f / (t0 + t1);
            pt0 = t0 * rt; pt1 = t1 * rt;
        }

        // v -> leaf probs; path = leaf * pl2 * pt written to smem
        float ks[8];
        #pragma unroll
        for (int g = 0; g < 8; ++g) ks[g] = pl2[g] * (g < 4 ? pt0 : pt1);

#define FINALIZE(G, A, B)                                       \
        {                                                       \
            float rc = grcp[G], kk = ks[G];                     \
            _Pragma("unroll")                                   \
            for (int i = A; i < B; ++i) {                       \
                v[i] *= rc;            /* leaf prob */          \
                rx[i] = v[i] * kk;     /* path prob */          \
            }                                                   \
        }
        FINALIZE(0,  0,  7)  FINALIZE(1,  7, 30)
        FINALIZE(2, 30, 48)  FINALIZE(3, 48, 53)
        FINALIZE(4, 53, 58)  FINALIZE(5, 58, 59)
        FINALIZE(6, 59, 62)  FINALIZE(7, 62, 65)
#undef FINALIZE
    }
    __syncwarp();

    // ---- Phase C: warp-coalesced stream of path probs: 520 float4 ----
    {
        float4* op4 = reinterpret_cast<float4*>(out_path + wrow0 * 65);
        const float4* b4 = reinterpret_cast<const float4*>(wbuf);
        #pragma unroll
        for (int k = 0; k < 17; ++k) {
            int idx = lane + k * 32;
            if (idx < 520) op4[idx] = b4[idx];
        }
    }
    __syncwarp();   // warp's path reads done before node overwrite

    // ---- Phase D: write node rows [32][76] from live registers ----
    {
        float* rn = wbuf + lane * 76;
        #pragma unroll
        for (int i = 0; i < 65; ++i) rn[i] = v[i];
        #pragma unroll
        for (int g = 0; g < 8; ++g) rn[65 + g] = pl2[g];
        rn[73] = pt0;
        rn[74] = pt1;
        rn[75] = 1.0f;
    }
    __syncwarp();

    // ---- Phase E: warp-coalesced stream of node rows: 32*76 = 608 float4 exact ----
    {
        float4* on4 = reinterpret_cast<float4*>(out_node + wrow0 * 76);
        const float4* b4 = reinterpret_cast<const float4*>(wbuf);
        #pragma unroll
        for (int k = 0; k < 19; ++k) {
            int idx = lane + k * 32;
            on4[idx] = b4[idx];
        }
    }
}

extern "C" void kernel_launch(void* const* d_in, const int* in_sizes, int n_in,
                              void* d_out, int out_size)
{
    const float* x = (const float*)d_in[0];
    const long long N = (long long)in_sizes[0] / 65;   // 524288
    float* out_path = (float*)d_out;
    float* out_node = out_path + N * 65;

    const int blocks = (int)(N / ROWS_B);              // 8192
    molemap_kernel<<<blocks, NT>>>(x, out_path, out_node);
}